// round 16
// baseline (speedup 1.0000x reference)
#include <cuda_runtime.h>

#define Lc 128
#define Sc 2048
#define Mh (Sc / 2)               // split: fwd covers t=1..Mh, bwd t=Sc-1..Mh+1
#define Bc 128
#define IGNORE_IDX (-100)
#define NT  512
#define PD  8                     // prefetch depth (power of 2)

__device__ float g_E [Lc * Lc];   // row-major: exp(trans[i][j])
__device__ float g_Et[Lc * Lc];   // transposed
__device__ float g_logz[Bc];
__device__ float g_score[Bc];

__global__ void prep_E(const float* __restrict__ trans) {
    int idx = blockIdx.x * blockDim.x + threadIdx.x;
    if (idx < Lc * Lc) {
        int i = idx >> 7, j = idx & (Lc - 1);
        float v = expf(trans[idx]);
        g_E[idx] = v;
        g_Et[j * Lc + i] = v;
    }
}

__device__ __forceinline__ void ffma2(unsigned long long& d,
                                      unsigned long long a,
                                      unsigned long long b) {
    asm("fma.rn.f32x2 %0, %1, %2, %0;" : "+l"(d) : "l"(a), "l"(b));
}
__device__ __forceinline__ unsigned long long fadd2(unsigned long long a,
                                                    unsigned long long b) {
    unsigned long long d;
    asm("add.rn.f32x2 %0, %1, %2;" : "=l"(d) : "l"(a), "l"(b));
    return d;
}

// exact power-of-two renorm: r -> (e = floor(log2 r), inv = 2^-e)
__device__ __forceinline__ float exp_strip(float r, int& e_out) {
    unsigned bits = __float_as_uint(r);
    int be = (int)(bits >> 23);
    e_out = be - 127;
    return __uint_as_float((unsigned)(254 - be) << 23);
}

// 64-length dot of smem half vs register-packed E half (32 u64 regs).
__device__ __forceinline__ float dot64(const float* base,
                                       const unsigned long long* Epk) {
    const ulonglong2* p2 = (const ulonglong2*)base;
    unsigned long long a0 = 0ull, a1 = 0ull, a2 = 0ull, a3 = 0ull;
#pragma unroll
    for (int k = 0; k < 16; k += 2) {
        ulonglong2 pv0 = p2[k];
        ulonglong2 pv1 = p2[k + 1];
        ffma2(a0, pv0.x, Epk[2 * k]);
        ffma2(a1, pv0.y, Epk[2 * k + 1]);
        ffma2(a2, pv1.x, Epk[2 * k + 2]);
        ffma2(a3, pv1.y, Epk[2 * k + 3]);
    }
    unsigned long long sm = fadd2(fadd2(a0, a2), fadd2(a1, a3));
    return __uint_as_float((unsigned)sm) +
           __uint_as_float((unsigned)(sm >> 32));
}

// ---------------------------------------------------------------------------
// ONE CTA per batch, 512 threads.
// Group 0 (tid 0-255): forward scan + gold score. Group 1 (tid 256-511): bwd.
// Within a group: warp gw, lane l -> state j = 16*gw + (l&15), half h = l>>4.
// Half-dot per thread, combined by shfl_xor(16); one named bar per step.
// ---------------------------------------------------------------------------
__global__ __launch_bounds__(NT, 1) void crf_scan(
    const float* __restrict__ em,
    const int* __restrict__ mask,
    const int* __restrict__ tags,
    const float* __restrict__ trans,
    const float* __restrict__ startt,
    const float* __restrict__ endt)
{
    const int b    = blockIdx.x;
    const int tid  = threadIdx.x;
    const int g    = tid >> 8;        // 0 = fwd, 1 = bwd
    const int gt   = tid & 255;       // tid within group
    const int gw   = gt >> 5;         // warp within group (0-7)
    const int l    = tid & 31;
    const int j    = (gw << 4) | (l & 15);
    const int h    = l >> 4;

    __shared__ __align__(16) float pbufF[2][Lc];
    __shared__ __align__(16) float pbufB[2][Lc];
    __shared__ float aMs[Lc], bMs[Lc];
    __shared__ float redf[8];
    __shared__ int   redi[8];
    __shared__ int   CiS[2];

#define GBAR() asm volatile("bar.sync %0, 256;" :: "r"(g + 1) : "memory")

    const int*   tg  = tags + (long long)b * Sc;
    const float* emb = em   + (long long)b * Sc * Lc;
    const int*   mk  = mask + (long long)b * Sc;

    float er[PD];
    int   mr[PD];
    int   Ci  = 0;
    int   cur = 0;

    if (g == 0) {
        // ---------------- gold-path score (256 threads, 8 iters) -----------
        float sc = 0.f;
        int lastIdx = -1;
        for (int t = gt; t < Sc; t += 256) {
            int tt = tg[t];
            bool v = (tt != IGNORE_IDX);
            int st = v ? tt : 0;
            if (v && t > lastIdx) lastIdx = t;
            if (t == 0) {
                if (v) sc += startt[st];
            } else if (v) {
                int tp = tg[t - 1];
                int sp = (tp != IGNORE_IDX) ? tp : 0;
                sc += trans[sp * Lc + st] + emb[(long long)t * Lc + st];
            }
        }
#pragma unroll
        for (int o = 16; o > 0; o >>= 1) {
            sc += __shfl_xor_sync(0xffffffffu, sc, o);
            lastIdx = max(lastIdx, __shfl_xor_sync(0xffffffffu, lastIdx, o));
        }
        if (l == 0) { redf[gw] = sc; redi[gw] = lastIdx; }
        GBAR();
        if (tid == 0) {
            float s = 0.f; int li = -1;
#pragma unroll
            for (int k = 0; k < 8; k++) { s += redf[k]; li = max(li, redi[k]); }
            if (li >= 0) {
                int lt = tg[li];
                s += endt[(lt != IGNORE_IDX) ? lt : 0];
            }
            g_score[b] = s;
        }

        // E half-column (transposed layout): rows 64h..64h+63 of column j
        unsigned long long Epk[32];
        {
            const ulonglong2* e2 = (const ulonglong2*)(g_Et + j * Lc + 64 * h);
#pragma unroll
            for (int k = 0; k < 16; k++) {
                ulonglong2 v = e2[k];
                Epk[2 * k] = v.x; Epk[2 * k + 1] = v.y;
            }
        }

        float pj = __expf(startt[j] + emb[j]);
        if (l < 16) pbufF[0][j] = pj;

#pragma unroll
        for (int d = 0; d < PD; d++) {
            er[d] = emb[(long long)(1 + d) * Lc + j];
            mr[d] = mk[1 + d];
        }
        const float* emp = emb + (long long)(1 + PD) * Lc + j;
        const int*   mkp = mk + 1 + PD;
        float exc_cur = __expf(er[0]);            // exp(em_1)
        GBAR();

#pragma unroll 8
        for (int t = 1; t <= Mh; ++t) {
            const int s = (t - 1) & (PD - 1);
            const int m = mr[s];
            float sfac = exc_cur;
            if ((t & 3) == 1) {                   // renorm every 4th step
                int e;
                float inv = exp_strip(pbufF[cur][0], e);
                Ci += m ? e : 0;
                sfac = exc_cur * inv;
            }
            float q = dot64(pbufF[cur] + 64 * h, Epk);
            q += __shfl_xor_sync(0xffffffffu, q, 16);   // combine halves
            pj = m ? q * sfac : pj;
            if (l < 16) pbufF[cur ^ 1][j] = pj;
            // tail: refill + next exp overlap the barrier wait
            er[s] = *emp;  emp += Lc;             // t+PD <= Mh+PD < Sc
            mr[s] = *mkp;  ++mkp;
            exc_cur = __expf(er[t & (PD - 1)]);   // exp(em_{t+1})
            GBAR();
            cur ^= 1;
        }
        if (l < 16) aMs[j] = pj;
        if (tid == 0) CiS[0] = Ci;

    } else {
        // E half-row (row-major layout): cols 64h..64h+63 of row j
        unsigned long long Epk[32];
        {
            const ulonglong2* e2 = (const ulonglong2*)(g_E + j * Lc + 64 * h);
#pragma unroll
            for (int k = 0; k < 16; k++) {
                ulonglong2 v = e2[k];
                Epk[2 * k] = v.x; Epk[2 * k + 1] = v.y;
            }
        }

        // init at t = Sc-1: beta = exp(end), d = exp(em_{Sc-1}) * beta
        float bj = __expf(endt[j]);
        if (l < 16)
            pbufB[0][j] = __expf(emb[(long long)(Sc - 1) * Lc + j]) * bj;

#pragma unroll
        for (int d = 0; d < PD; d++) {
            er[d] = emb[(long long)(Sc - 2 - d) * Lc + j];
            mr[d] = mk[Sc - 1 - d];
        }
        const float* emp = emb + (long long)(Sc - 2 - PD) * Lc + j;
        const int*   mkp = mk + (Sc - 1 - PD);
        float exc_cur = __expf(er[0]);            // exp(em_{Sc-2})
        GBAR();

#pragma unroll 8
        for (int s = 0; s < Mh - 1; ++s) {        // t = Sc-1-s down to Mh+1
            const int sl = s & (PD - 1);
            const int m = mr[sl];                 // mask_t
            float inv = 1.0f;
            if ((s & 3) == 0) {                   // renorm every 4th step
                int e;
                inv = exp_strip(pbufB[cur][0], e);
                Ci += m ? e : 0;
            }
            float q = dot64(pbufB[cur] + 64 * h, Epk);
            q += __shfl_xor_sync(0xffffffffu, q, 16);   // combine halves
            float bn = m ? ((s & 3) == 0 ? q * inv : q) : bj;
            bj = bn;
            if (l < 16) pbufB[cur ^ 1][j] = bn * exc_cur;  // exp(em_{t-1})
            // tail: refill + next exp overlap the barrier wait
            er[sl] = *emp;  emp -= Lc;            // tp >= 1016 >= 0
            mr[sl] = *mkp;  --mkp;
            exc_cur = __expf(er[(s + 1) & (PD - 1)]);  // exp(em_{t-2})
            GBAR();
            cur ^= 1;
        }
        if (l < 16) bMs[j] = bj;                  // beta at t = Mh
        if (gt == 0) CiS[1] = Ci;
    }

    // ---------------- in-CTA combine (warp 0 only) ----------------
    __syncthreads();
    if (tid < 32) {
        float v = 0.f;
#pragma unroll
        for (int k = 0; k < 4; k++) {
            int idx = tid + 32 * k;
            v += aMs[idx] * bMs[idx];
        }
#pragma unroll
        for (int o = 16; o > 0; o >>= 1) v += __shfl_xor_sync(0xffffffffu, v, o);
        if (tid == 0) {
            double Csum = (double)(CiS[0] + CiS[1]) * 0.6931471805599453;
            g_logz[b] = (float)(Csum + (double)logf(v));
        }
    }
#undef GBAR
}

// ---------------------------------------------------------------------------
__global__ void final_reduce(float* __restrict__ out) {
    int j = threadIdx.x;
    float v = g_logz[j] - g_score[j];
#pragma unroll
    for (int o = 16; o > 0; o >>= 1) v += __shfl_xor_sync(0xffffffffu, v, o);
    __shared__ float red[4];
    if ((j & 31) == 0) red[j >> 5] = v;
    __syncthreads();
    if (j == 0) out[0] = (red[0] + red[1] + red[2] + red[3]) * (1.0f / (float)Bc);
}

// ---------------------------------------------------------------------------
extern "C" void kernel_launch(void* const* d_in, const int* in_sizes, int n_in,
                              void* d_out, int out_size) {
    const float* em     = (const float*)d_in[0];
    const int*   mask   = (const int*)d_in[1];
    const int*   tags   = (const int*)d_in[2];
    const float* trans  = (const float*)d_in[3];
    const float* startt = (const float*)d_in[4];
    const float* endt   = (const float*)d_in[5];
    (void)in_sizes; (void)n_in; (void)out_size;

    prep_E<<<(Lc * Lc + 255) / 256, 256>>>(trans);
    crf_scan<<<Bc, NT>>>(em, mask, tags, trans, startt, endt);
    final_reduce<<<1, 128>>>((float*)d_out);
}